// round 1
// baseline (speedup 1.0000x reference)
#include <cuda_runtime.h>
#include <cuda_bf16.h>
#include <math.h>

#define B_  8
#define S_  1024
#define H_  1024
#define NH_ 16
#define HD_ 64
#define BH_ (B_*NH_)   // 128

// Scratch: Q,K,V in [B,NH,S,HD] layout. 32MB each.
__device__ float g_q[(size_t)B_*NH_*S_*HD_];
__device__ float g_k[(size_t)B_*NH_*S_*HD_];
__device__ float g_v[(size_t)B_*NH_*S_*HD_];

// ---------------------------------------------------------------------------
// Kernel 1: QKV = X @ W + b, scattered into g_q/g_k/g_v ([B,NH,S,HD])
// M=8192, N=3072, K=1024. 128x128x16 tiles, 256 threads, 8x8 micro-tile.
// ---------------------------------------------------------------------------
__global__ __launch_bounds__(256)
void qkv_gemm_kernel(const float* __restrict__ X,
                     const float* __restrict__ W,
                     const float* __restrict__ bias) {
    const int BM = 128, BN = 128, BK = 16;
    __shared__ float As[16][132];   // [k][m], pad 4
    __shared__ float Bs[16][128];   // [k][n]

    const int bm = blockIdx.y * BM;
    const int bn = blockIdx.x * BN;
    const int tid = threadIdx.x;
    const int tx = tid & 15;        // n direction
    const int ty = tid >> 4;        // m direction

    float acc[8][8];
#pragma unroll
    for (int i = 0; i < 8; i++)
#pragma unroll
        for (int j = 0; j < 8; j++) acc[i][j] = 0.f;

    for (int k0 = 0; k0 < 1024; k0 += BK) {
        // Load A tile [128 m][16 k] -> As[k][m]  (2 float4 per thread)
#pragma unroll
        for (int r = 0; r < 2; r++) {
            int l = tid + 256 * r;          // 0..511 float4 chunks
            int row = l >> 2;               // 0..127 (m)
            int kc  = (l & 3) << 2;         // 0,4,8,12
            float4 v = *(const float4*)(X + (size_t)(bm + row) * 1024 + k0 + kc);
            As[kc + 0][row] = v.x;
            As[kc + 1][row] = v.y;
            As[kc + 2][row] = v.z;
            As[kc + 3][row] = v.w;
        }
        // Load B tile [16 k][128 n] -> Bs[k][n]
#pragma unroll
        for (int r = 0; r < 2; r++) {
            int l = tid + 256 * r;          // 0..511
            int row = l >> 5;               // 0..15 (k)
            int col = (l & 31) << 2;        // 0..124
            float4 v = *(const float4*)(W + (size_t)(k0 + row) * 3072 + bn + col);
            *(float4*)&Bs[row][col] = v;
        }
        __syncthreads();

#pragma unroll
        for (int kk = 0; kk < BK; kk++) {
            float a[8], b[8];
#pragma unroll
            for (int i = 0; i < 8; i++) a[i] = As[kk][ty * 8 + i];
#pragma unroll
            for (int j = 0; j < 8; j++) b[j] = Bs[kk][tx * 8 + j];
#pragma unroll
            for (int i = 0; i < 8; i++)
#pragma unroll
                for (int j = 0; j < 8; j++) acc[i][j] += a[i] * b[j];
        }
        __syncthreads();
    }

    // Epilogue: bias + scatter to g_q/g_k/g_v
    float bcache[8];
#pragma unroll
    for (int j = 0; j < 8; j++) bcache[j] = bias[bn + tx * 8 + j];

#pragma unroll
    for (int i = 0; i < 8; i++) {
        int m = bm + ty * 8 + i;
        int b = m >> 10;           // /1024
        int s = m & 1023;
#pragma unroll
        for (int j = 0; j < 8; j++) {
            int n = bn + tx * 8 + j;
            float val = acc[i][j] + bcache[j];
            int nh    = n / 192;
            int rem   = n - nh * 192;
            int which = rem >> 6;
            int hd    = rem & 63;
            size_t dst = (((size_t)b * NH_ + nh) * S_ + s) * HD_ + hd;
            if (which == 0)      g_q[dst] = val;
            else if (which == 1) g_k[dst] = val;
            else                 g_v[dst] = val;
        }
    }
}

// ---------------------------------------------------------------------------
// Kernel 2: fused attention. One block = (b,h) x 64-query tile.
// Online softmax over 16 key-tiles of 64. 256 threads, 4x4 micro-tiles.
// Reference semantics: scores = (q.k)*8 ; where mask!=0 -> -10000 ; softmax ; @V
// ---------------------------------------------------------------------------
__global__ __launch_bounds__(256)
void attn_kernel(const int* __restrict__ mask, float* __restrict__ out) {
    extern __shared__ float sm[];
    float* Qs = sm;                 // [d][q] : 64 x 65  (pre-scaled by 8)
    float* Ks = Qs + 64 * 65;       // [d][k] : 64 x 65
    float* Vs = Ks + 64 * 65;       // [k][d] : 64 x 65
    float* Ps = Vs + 64 * 65;       // [k][q] : 64 x 65
    int*   mk = (int*)(Ps + 64 * 65);  // [1024]

    const int bh = blockIdx.y;          // 0..127
    const int b  = bh >> 4;
    const int nh = bh & 15;
    const int q0 = blockIdx.x * 64;
    const int tid = threadIdx.x;
    const int tx = tid & 15;            // key / hd direction
    const int ty = tid >> 4;            // query direction

    // Load Q tile (transposed to [d][q]), pre-scaled by sqrt(HD)=8
    const float* qg = g_q + ((size_t)bh * S_ + q0) * HD_;
#pragma unroll
    for (int r = 0; r < 4; r++) {
        int cc = tid + 256 * r;         // 0..1023 float4 chunks
        int qq = cc >> 4;               // 0..63
        int dd = (cc & 15) << 2;        // 0..60
        float4 v = *(const float4*)(qg + qq * HD_ + dd);
        Qs[(dd + 0) * 65 + qq] = v.x * 8.f;
        Qs[(dd + 1) * 65 + qq] = v.y * 8.f;
        Qs[(dd + 2) * 65 + qq] = v.z * 8.f;
        Qs[(dd + 3) * 65 + qq] = v.w * 8.f;
    }
    // Load mask row for this batch
#pragma unroll
    for (int r = 0; r < 4; r++) {
        int j = tid + 256 * r;
        mk[j] = mask[b * S_ + j];
    }

    float o[4][4];
    float mrow[4], lrow[4];
#pragma unroll
    for (int i = 0; i < 4; i++) {
        mrow[i] = -INFINITY;
        lrow[i] = 0.f;
#pragma unroll
        for (int j = 0; j < 4; j++) o[i][j] = 0.f;
    }

    for (int kt = 0; kt < 16; kt++) {
        const float* kg = g_k + ((size_t)bh * S_ + kt * 64) * HD_;
        const float* vg = g_v + ((size_t)bh * S_ + kt * 64) * HD_;
        __syncthreads();   // protect Ks/Vs/Ps from previous iteration readers
        // K tile -> Ks[d][k]
#pragma unroll
        for (int r = 0; r < 4; r++) {
            int cc = tid + 256 * r;
            int kk = cc >> 4;
            int dd = (cc & 15) << 2;
            float4 v = *(const float4*)(kg + kk * HD_ + dd);
            Ks[(dd + 0) * 65 + kk] = v.x;
            Ks[(dd + 1) * 65 + kk] = v.y;
            Ks[(dd + 2) * 65 + kk] = v.z;
            Ks[(dd + 3) * 65 + kk] = v.w;
        }
        // V tile -> Vs[k][d]
#pragma unroll
        for (int r = 0; r < 4; r++) {
            int cc = tid + 256 * r;
            int kk = cc >> 4;
            int dd = (cc & 15) << 2;
            float4 v = *(const float4*)(vg + kk * HD_ + dd);
            Vs[kk * 65 + dd + 0] = v.x;
            Vs[kk * 65 + dd + 1] = v.y;
            Vs[kk * 65 + dd + 2] = v.z;
            Vs[kk * 65 + dd + 3] = v.w;
        }
        __syncthreads();

        // scores s[4q][4k] = Q(scaled) . K
        float s[4][4];
#pragma unroll
        for (int i = 0; i < 4; i++)
#pragma unroll
            for (int j = 0; j < 4; j++) s[i][j] = 0.f;

#pragma unroll 16
        for (int d = 0; d < 64; d++) {
            float a[4], bb[4];
#pragma unroll
            for (int i = 0; i < 4; i++) a[i]  = Qs[d * 65 + ty * 4 + i];
#pragma unroll
            for (int j = 0; j < 4; j++) bb[j] = Ks[d * 65 + tx * 4 + j];
#pragma unroll
            for (int i = 0; i < 4; i++)
#pragma unroll
                for (int j = 0; j < 4; j++) s[i][j] += a[i] * bb[j];
        }

        // mask (mask!=0 -> -10000), per key column
        int kb = kt * 64 + tx * 4;
#pragma unroll
        for (int j = 0; j < 4; j++) {
            if (mk[kb + j] != 0) {
#pragma unroll
                for (int i = 0; i < 4; i++) s[i][j] = -10000.f;
            }
        }

        // online softmax update per query row (reduce across 16 tx lanes)
#pragma unroll
        for (int i = 0; i < 4; i++) {
            float rm = s[i][0];
            rm = fmaxf(rm, s[i][1]); rm = fmaxf(rm, s[i][2]); rm = fmaxf(rm, s[i][3]);
#pragma unroll
            for (int off = 8; off > 0; off >>= 1)
                rm = fmaxf(rm, __shfl_xor_sync(0xffffffffu, rm, off));
            float mn   = fmaxf(mrow[i], rm);
            float corr = __expf(mrow[i] - mn);   // exp(-inf - finite) = 0 on first tile
            float rs = 0.f;
#pragma unroll
            for (int j = 0; j < 4; j++) {
                s[i][j] = __expf(s[i][j] - mn);
                rs += s[i][j];
            }
#pragma unroll
            for (int off = 8; off > 0; off >>= 1)
                rs += __shfl_xor_sync(0xffffffffu, rs, off);
            lrow[i] = lrow[i] * corr + rs;
            mrow[i] = mn;
#pragma unroll
            for (int j = 0; j < 4; j++) o[i][j] *= corr;
        }

        // stash P transposed: Ps[k][q]
#pragma unroll
        for (int i = 0; i < 4; i++)
#pragma unroll
            for (int j = 0; j < 4; j++)
                Ps[(tx * 4 + j) * 65 + ty * 4 + i] = s[i][j];
        __syncthreads();

        // O += P @ V
#pragma unroll 16
        for (int kk = 0; kk < 64; kk++) {
            float a[4], bb[4];
#pragma unroll
            for (int i = 0; i < 4; i++) a[i]  = Ps[kk * 65 + ty * 4 + i];
#pragma unroll
            for (int j = 0; j < 4; j++) bb[j] = Vs[kk * 65 + tx * 4 + j];
#pragma unroll
            for (int i = 0; i < 4; i++)
#pragma unroll
                for (int j = 0; j < 4; j++) o[i][j] += a[i] * bb[j];
        }
    }

    // write context: out[b, q, nh*64+hd]
#pragma unroll
    for (int i = 0; i < 4; i++) {
        float inv = 1.f / lrow[i];
        size_t row = (size_t)(b * S_ + q0 + ty * 4 + i) * H_;
#pragma unroll
        for (int j = 0; j < 4; j++)
            out[row + nh * 64 + tx * 4 + j] = o[i][j] * inv;
    }
}

// ---------------------------------------------------------------------------
extern "C" void kernel_launch(void* const* d_in, const int* in_sizes, int n_in,
                              void* d_out, int out_size) {
    const float* hidden = (const float*)d_in[0];   // [8,1024,1024]
    const int*   mask   = (const int*)  d_in[1];   // [8,1,1,1024]
    const float* w_qkv  = (const float*)d_in[2];   // [1024,3072]
    const float* b_qkv  = (const float*)d_in[3];   // [3072]
    float* out = (float*)d_out;

    (void)in_sizes; (void)n_in; (void)out_size;

    dim3 g1(3072 / 128, 8192 / 128);               // 24 x 64
    qkv_gemm_kernel<<<g1, 256>>>(hidden, w_qkv, b_qkv);

    size_t smem = (size_t)4 * 64 * 65 * sizeof(float) + 1024 * sizeof(int); // 70656 B
    cudaFuncSetAttribute(attn_kernel, cudaFuncAttributeMaxDynamicSharedMemorySize,
                         (int)smem);
    dim3 g2(S_ / 64, BH_);                          // 16 x 128
    attn_kernel<<<g2, 256, smem>>>(mask, out);
}

// round 2
// speedup vs baseline: 1.8152x; 1.8152x over previous
#include <cuda_runtime.h>
#include <cuda_bf16.h>
#include <math.h>

#define B_  8
#define S_  1024
#define H_  1024
#define NH_ 16
#define HD_ 64
#define BH_ (B_*NH_)   // 128

// Scratch: Q,K,V in [B,NH,S,HD] layout. 32MB each.
__device__ float g_q[(size_t)B_*NH_*S_*HD_];
__device__ float g_k[(size_t)B_*NH_*S_*HD_];
__device__ float g_v[(size_t)B_*NH_*S_*HD_];

// ---------------------------------------------------------------------------
// tf32 helpers
// ---------------------------------------------------------------------------
__device__ __forceinline__ unsigned f2t(float x) {
    unsigned u;
    asm("cvt.rna.tf32.f32 %0, %1;" : "=r"(u) : "f"(x));
    return u;
}
// split fp32 into tf32 hi + residual lo (lo fed as raw fp32 bits; HW truncation
// of lo's low mantissa costs ~2^-23 relative — negligible)
__device__ __forceinline__ void split2(float x, unsigned& hi, unsigned& lo) {
    hi = f2t(x);
    lo = __float_as_uint(x - __uint_as_float(hi));
}
__device__ __forceinline__ void mma_t(float* d, const unsigned* a, const unsigned* b) {
    asm volatile(
        "mma.sync.aligned.m16n8k8.row.col.f32.tf32.tf32.f32 "
        "{%0,%1,%2,%3}, {%4,%5,%6,%7}, {%8,%9}, {%0,%1,%2,%3};\n"
        : "+f"(d[0]), "+f"(d[1]), "+f"(d[2]), "+f"(d[3])
        : "r"(a[0]), "r"(a[1]), "r"(a[2]), "r"(a[3]), "r"(b[0]), "r"(b[1]));
}

// ---------------------------------------------------------------------------
// Kernel 1: QKV = X @ W + b (tf32x3), scatter into g_q/g_k/g_v [B,NH,S,HD]
// M=8192 N=3072 K=1024. 128x128x32 block tile, 4 warps, 64x64 warp tile.
// ---------------------------------------------------------------------------
#define ASTR 137   // odd stride -> conflict-free transposed staging
#define BSTR 136

__global__ __launch_bounds__(128)
void qkv_gemm_kernel(const float* __restrict__ X,
                     const float* __restrict__ W,
                     const float* __restrict__ bias) {
    __shared__ float As[32 * ASTR];   // [k][m] fp32
    __shared__ float Bs[32 * BSTR];   // [k][n] fp32

    const int tid  = threadIdx.x;
    const int warp = tid >> 5, lane = tid & 31;
    const int g = lane >> 2, tg = lane & 3;
    const int wm = (warp & 1) * 64, wn = (warp >> 1) * 64;
    const int bm = blockIdx.y * 128, bn = blockIdx.x * 128;

    float acc[4][8][4];
#pragma unroll
    for (int mt = 0; mt < 4; mt++)
#pragma unroll
        for (int nt = 0; nt < 8; nt++)
#pragma unroll
            for (int i = 0; i < 4; i++) acc[mt][nt][i] = 0.f;

    for (int k0 = 0; k0 < 1024; k0 += 32) {
        // stage A tile [128m x 32k] -> As[k][m] (transposed scalar stores, CF)
#pragma unroll
        for (int r = 0; r < 8; r++) {
            int l = tid + 128 * r;
            int row = l >> 3, kc = (l & 7) << 2;
            float4 v = *(const float4*)(X + (size_t)(bm + row) * 1024 + k0 + kc);
            As[(kc + 0) * ASTR + row] = v.x;
            As[(kc + 1) * ASTR + row] = v.y;
            As[(kc + 2) * ASTR + row] = v.z;
            As[(kc + 3) * ASTR + row] = v.w;
        }
        // stage B tile [32k x 128n] -> Bs[k][n] (vector stores)
#pragma unroll
        for (int r = 0; r < 8; r++) {
            int l = tid + 128 * r;
            int row = l >> 5, col = (l & 31) << 2;
            *(float4*)&Bs[row * BSTR + col] =
                *(const float4*)(W + (size_t)(k0 + row) * 3072 + bn + col);
        }
        __syncthreads();

#pragma unroll
        for (int ks = 0; ks < 4; ks++) {
            int kb = ks * 8;
            unsigned ah[4][4], al[4][4];
#pragma unroll
            for (int mt = 0; mt < 4; mt++) {
                int m = wm + mt * 16 + g;
                float x0 = As[(kb + tg) * ASTR + m];
                float x1 = As[(kb + tg) * ASTR + m + 8];
                float x2 = As[(kb + tg + 4) * ASTR + m];
                float x3 = As[(kb + tg + 4) * ASTR + m + 8];
                split2(x0, ah[mt][0], al[mt][0]);
                split2(x1, ah[mt][1], al[mt][1]);
                split2(x2, ah[mt][2], al[mt][2]);
                split2(x3, ah[mt][3], al[mt][3]);
            }
#pragma unroll
            for (int nt = 0; nt < 8; nt++) {
                int n = wn + nt * 8 + g;
                float y0 = Bs[(kb + tg) * BSTR + n];
                float y1 = Bs[(kb + tg + 4) * BSTR + n];
                unsigned bh[2], bl[2];
                split2(y0, bh[0], bl[0]);
                split2(y1, bh[1], bl[1]);
#pragma unroll
                for (int mt = 0; mt < 4; mt++) {
                    mma_t(acc[mt][nt], ah[mt], bh);   // hi*hi
                    mma_t(acc[mt][nt], ah[mt], bl);   // hi*lo
                    mma_t(acc[mt][nt], al[mt], bh);   // lo*hi
                }
            }
        }
        __syncthreads();
    }

    // epilogue: bias + scatter (pairs of adjacent cols share q/k/v target)
#pragma unroll
    for (int nt = 0; nt < 8; nt++) {
        int n0 = bn + wn + nt * 8 + 2 * tg;
        float bia0 = bias[n0], bia1 = bias[n0 + 1];
        int nh  = n0 / 192;
        int rem = n0 - nh * 192;
        int which = rem >> 6;
        int hd = rem & 63;
        float* basep = (which == 0) ? g_q : ((which == 1) ? g_k : g_v);
#pragma unroll
        for (int mt = 0; mt < 4; mt++) {
            int m0 = bm + wm + mt * 16 + g;
#pragma unroll
            for (int h = 0; h < 2; h++) {
                int m = m0 + h * 8;
                int b = m >> 10, s = m & 1023;
                float2 v;
                v.x = acc[mt][nt][h * 2 + 0] + bia0;
                v.y = acc[mt][nt][h * 2 + 1] + bia1;
                *(float2*)(basep + (((size_t)(b * NH_ + nh)) * S_ + s) * HD_ + hd) = v;
            }
        }
    }
}

// ---------------------------------------------------------------------------
// Kernel 2: fused flash attention, tf32x3 QK / tf32 PV.
// Block = (b,h) x 128-query tile. 4 warps x 32 queries. 16 key-tiles of 64.
// ---------------------------------------------------------------------------
#define QT 128
#define QSTR 68   // conflict-free for A-fragment loads
#define KSTR 72   // conflict-free for B-fragment loads

__global__ __launch_bounds__(128)
void attn_kernel(const int* __restrict__ mask, float* __restrict__ out) {
    extern __shared__ char smc[];
    float*    Qs = (float*)smc;                  // [128][68] fp32 (pre-scaled x8)
    float*    Ks = Qs + QT * QSTR;               // [64][72] fp32
    unsigned* Vt = (unsigned*)(Ks + 64 * KSTR);  // [64][72] tf32
    unsigned* Ps = Vt + 64 * KSTR;               // [128][68] tf32
    int*      mk = (int*)(Ps + QT * QSTR);       // [1024]

    const int bh = blockIdx.y, b = bh >> 4, nh = bh & 15;
    const int q0 = blockIdx.x * QT;
    const int tid = threadIdx.x;
    const int warp = tid >> 5, lane = tid & 31;
    const int g = lane >> 2, tg = lane & 3;
    const int wq = warp * 32;

    // load Q (x8 scale) and mask
    const float* qg = g_q + ((size_t)bh * S_ + q0) * HD_;
#pragma unroll
    for (int r = 0; r < 16; r++) {
        int cc = tid + 128 * r;
        int q = cc >> 4, d = (cc & 15) << 2;
        float4 v = *(const float4*)(qg + q * 64 + d);
        v.x *= 8.f; v.y *= 8.f; v.z *= 8.f; v.w *= 8.f;
        *(float4*)&Qs[q * QSTR + d] = v;
    }
#pragma unroll
    for (int r = 0; r < 8; r++) {
        int j = tid + 128 * r;
        mk[j] = mask[b * S_ + j];
    }

    float O[2][8][4];
    float mrow[2][2], lrow[2][2];
#pragma unroll
    for (int mt = 0; mt < 2; mt++) {
        mrow[mt][0] = -INFINITY; mrow[mt][1] = -INFINITY;
        lrow[mt][0] = 0.f;       lrow[mt][1] = 0.f;
#pragma unroll
        for (int nt = 0; nt < 8; nt++)
#pragma unroll
            for (int i = 0; i < 4; i++) O[mt][nt][i] = 0.f;
    }

    for (int kt = 0; kt < 16; kt++) {
        __syncthreads();   // Q/mask ready (kt=0); Ks/Vt consumers done (kt>0)
        const float* kg = g_k + ((size_t)bh * S_ + kt * 64) * HD_;
        const float* vg = g_v + ((size_t)bh * S_ + kt * 64) * HD_;
#pragma unroll
        for (int r = 0; r < 8; r++) {
            int cc = tid + 128 * r;
            int key = cc >> 4, d = (cc & 15) << 2;
            *(float4*)&Ks[key * KSTR + d] =
                *(const float4*)(kg + key * 64 + d);
            float4 v = *(const float4*)(vg + key * 64 + d);
            uint4 u;
            u.x = f2t(v.x); u.y = f2t(v.y); u.z = f2t(v.z); u.w = f2t(v.w);
            *(uint4*)&Vt[key * KSTR + d] = u;
        }
        __syncthreads();

        // ---- S = (Q*8) @ K^T  (tf32x3) ----
        float S[2][8][4];
#pragma unroll
        for (int mt = 0; mt < 2; mt++)
#pragma unroll
            for (int nt = 0; nt < 8; nt++)
#pragma unroll
                for (int i = 0; i < 4; i++) S[mt][nt][i] = 0.f;

#pragma unroll
        for (int ks = 0; ks < 8; ks++) {
            int kb = ks * 8;
            unsigned ah[2][4], al[2][4];
#pragma unroll
            for (int mt = 0; mt < 2; mt++) {
                int rr = (wq + mt * 16 + g) * QSTR;
                float x0 = Qs[rr + kb + tg];
                float x1 = Qs[rr + 8 * QSTR + kb + tg];
                float x2 = Qs[rr + kb + tg + 4];
                float x3 = Qs[rr + 8 * QSTR + kb + tg + 4];
                split2(x0, ah[mt][0], al[mt][0]);
                split2(x1, ah[mt][1], al[mt][1]);
                split2(x2, ah[mt][2], al[mt][2]);
                split2(x3, ah[mt][3], al[mt][3]);
            }
#pragma unroll
            for (int nt = 0; nt < 8; nt++) {
                float y0 = Ks[(nt * 8 + g) * KSTR + kb + tg];
                float y1 = Ks[(nt * 8 + g) * KSTR + kb + tg + 4];
                unsigned bhf[2], blf[2];
                split2(y0, bhf[0], blf[0]);
                split2(y1, bhf[1], blf[1]);
#pragma unroll
                for (int mt = 0; mt < 2; mt++) {
                    mma_t(S[mt][nt], ah[mt], bhf);
                    mma_t(S[mt][nt], ah[mt], blf);
                    mma_t(S[mt][nt], al[mt], bhf);
                }
            }
        }

        // ---- mask ----
#pragma unroll
        for (int nt = 0; nt < 8; nt++) {
            int c = kt * 64 + nt * 8 + 2 * tg;
            if (mk[c]) {
                S[0][nt][0] = -10000.f; S[0][nt][2] = -10000.f;
                S[1][nt][0] = -10000.f; S[1][nt][2] = -10000.f;
            }
            if (mk[c + 1]) {
                S[0][nt][1] = -10000.f; S[0][nt][3] = -10000.f;
                S[1][nt][1] = -10000.f; S[1][nt][3] = -10000.f;
            }
        }

        // ---- online softmax (rows warp-local; reduce over tg group) ----
#pragma unroll
        for (int mt = 0; mt < 2; mt++)
#pragma unroll
        for (int h = 0; h < 2; h++) {
            float rm = -INFINITY;
#pragma unroll
            for (int nt = 0; nt < 8; nt++)
                rm = fmaxf(rm, fmaxf(S[mt][nt][2 * h], S[mt][nt][2 * h + 1]));
            rm = fmaxf(rm, __shfl_xor_sync(0xffffffffu, rm, 1));
            rm = fmaxf(rm, __shfl_xor_sync(0xffffffffu, rm, 2));
            float mn = fmaxf(mrow[mt][h], rm);
            float corr = __expf(mrow[mt][h] - mn);
            mrow[mt][h] = mn;
            float rs = 0.f;
#pragma unroll
            for (int nt = 0; nt < 8; nt++) {
                float e0 = __expf(S[mt][nt][2 * h] - mn);
                float e1 = __expf(S[mt][nt][2 * h + 1] - mn);
                S[mt][nt][2 * h] = e0; S[mt][nt][2 * h + 1] = e1;
                rs += e0 + e1;
            }
            rs += __shfl_xor_sync(0xffffffffu, rs, 1);
            rs += __shfl_xor_sync(0xffffffffu, rs, 2);
            lrow[mt][h] = lrow[mt][h] * corr + rs;
#pragma unroll
            for (int nt = 0; nt < 8; nt++) {
                O[mt][nt][2 * h]     *= corr;
                O[mt][nt][2 * h + 1] *= corr;
            }
        }

        // ---- stash P as tf32 (warp-private rows -> no block barrier) ----
#pragma unroll
        for (int mt = 0; mt < 2; mt++)
#pragma unroll
        for (int h = 0; h < 2; h++) {
            int row = wq + mt * 16 + g + h * 8;
#pragma unroll
            for (int nt = 0; nt < 8; nt++) {
                uint2 u;
                u.x = f2t(S[mt][nt][2 * h]);
                u.y = f2t(S[mt][nt][2 * h + 1]);
                *(uint2*)&Ps[row * QSTR + nt * 8 + 2 * tg] = u;
            }
        }
        __syncwarp();

        // ---- O += P @ V  (plain tf32) ----
#pragma unroll
        for (int kc = 0; kc < 8; kc++) {
            unsigned ap[2][4];
#pragma unroll
            for (int mt = 0; mt < 2; mt++) {
                int rr = (wq + mt * 16 + g) * QSTR;
                ap[mt][0] = Ps[rr + kc * 8 + tg];
                ap[mt][1] = Ps[rr + 8 * QSTR + kc * 8 + tg];
                ap[mt][2] = Ps[rr + kc * 8 + tg + 4];
                ap[mt][3] = Ps[rr + 8 * QSTR + kc * 8 + tg + 4];
            }
#pragma unroll
            for (int nt = 0; nt < 8; nt++) {
                unsigned bv[2];
                bv[0] = Vt[(kc * 8 + tg) * KSTR + nt * 8 + g];
                bv[1] = Vt[(kc * 8 + tg + 4) * KSTR + nt * 8 + g];
#pragma unroll
                for (int mt = 0; mt < 2; mt++)
                    mma_t(O[mt][nt], ap[mt], bv);
            }
        }
    }

    // epilogue: out[b, q, nh*64 + d]
#pragma unroll
    for (int mt = 0; mt < 2; mt++)
#pragma unroll
    for (int h = 0; h < 2; h++) {
        float inv = 1.f / lrow[mt][h];
        int q = q0 + wq + mt * 16 + g + h * 8;
        float* op = out + ((size_t)(b * S_ + q)) * H_ + nh * 64;
#pragma unroll
        for (int nt = 0; nt < 8; nt++) {
            float2 v;
            v.x = O[mt][nt][2 * h] * inv;
            v.y = O[mt][nt][2 * h + 1] * inv;
            *(float2*)(op + nt * 8 + 2 * tg) = v;
        }
    }
}

// ---------------------------------------------------------------------------
extern "C" void kernel_launch(void* const* d_in, const int* in_sizes, int n_in,
                              void* d_out, int out_size) {
    const float* hidden = (const float*)d_in[0];   // [8,1024,1024]
    const int*   mask   = (const int*)  d_in[1];   // [8,1,1,1024]
    const float* w_qkv  = (const float*)d_in[2];   // [1024,3072]
    const float* b_qkv  = (const float*)d_in[3];   // [3072]
    float* out = (float*)d_out;

    (void)in_sizes; (void)n_in; (void)out_size;

    dim3 g1(3072 / 128, 8192 / 128);               // 24 x 64
    qkv_gemm_kernel<<<g1, 128>>>(hidden, w_qkv, b_qkv);

    size_t smem = (size_t)(QT * QSTR + 64 * KSTR + 64 * KSTR + QT * QSTR) * 4
                + 1024 * sizeof(int);              // 110592 B
    cudaFuncSetAttribute(attn_kernel, cudaFuncAttributeMaxDynamicSharedMemorySize,
                         (int)smem);
    dim3 g2(S_ / QT, BH_);                          // 8 x 128
    attn_kernel<<<g2, 128, smem>>>(mask, out);
}

// round 3
// speedup vs baseline: 3.2718x; 1.8024x over previous
#include <cuda_runtime.h>
#include <cuda_fp16.h>
#include <math.h>

#define B_  8
#define S_  1024
#define H_  1024
#define NH_ 16
#define HD_ 64
#define BH_ (B_*NH_)   // 128

// Scratch: Q,K,V in [B,NH,S,HD] layout. 32MB each.
__device__ float g_q[(size_t)B_*NH_*S_*HD_];
__device__ float g_k[(size_t)B_*NH_*S_*HD_];
__device__ float g_v[(size_t)B_*NH_*S_*HD_];

// ---------------------------------------------------------------------------
// helpers
// ---------------------------------------------------------------------------
__device__ __forceinline__ unsigned smem_u32(const void* p) {
    return (unsigned)__cvta_generic_to_shared(p);
}
__device__ __forceinline__ void ldm_x4(unsigned* r, unsigned addr) {
    asm volatile("ldmatrix.sync.aligned.m8n8.x4.shared.b16 {%0,%1,%2,%3}, [%4];"
        : "=r"(r[0]), "=r"(r[1]), "=r"(r[2]), "=r"(r[3]) : "r"(addr));
}
__device__ __forceinline__ void ldm_x4t(unsigned* r, unsigned addr) {
    asm volatile("ldmatrix.sync.aligned.m8n8.x4.trans.shared.b16 {%0,%1,%2,%3}, [%4];"
        : "=r"(r[0]), "=r"(r[1]), "=r"(r[2]), "=r"(r[3]) : "r"(addr));
}
__device__ __forceinline__ void mma16(float* d, const unsigned* a, const unsigned* b) {
    asm volatile(
        "mma.sync.aligned.m16n8k16.row.col.f32.f16.f16.f32 "
        "{%0,%1,%2,%3}, {%4,%5,%6,%7}, {%8,%9}, {%0,%1,%2,%3};\n"
        : "+f"(d[0]), "+f"(d[1]), "+f"(d[2]), "+f"(d[3])
        : "r"(a[0]), "r"(a[1]), "r"(a[2]), "r"(a[3]), "r"(b[0]), "r"(b[1]));
}
// split float4 -> hi/lo fp16 pairs, store 4 contiguous halfs in each array
__device__ __forceinline__ void cvt_store(__half* Hh, __half* Hl, int idx, float4 v) {
    __half2 h0 = __float22half2_rn(make_float2(v.x, v.y));
    __half2 h1 = __float22half2_rn(make_float2(v.z, v.w));
    float2 f0 = __half22float2(h0), f1 = __half22float2(h1);
    __half2 l0 = __float22half2_rn(make_float2(v.x - f0.x, v.y - f0.y));
    __half2 l1 = __float22half2_rn(make_float2(v.z - f1.x, v.w - f1.y));
    *(__half2*)(Hh + idx)     = h0;
    *(__half2*)(Hh + idx + 2) = h1;
    *(__half2*)(Hl + idx)     = l0;
    *(__half2*)(Hl + idx + 2) = l1;
}

// ---------------------------------------------------------------------------
// Kernel 1: QKV = X @ W + b (fp16x2, 3 passes), scatter into g_q/g_k/g_v
// M=8192 N=3072 K=1024. 128x128x32 tile, 4 warps, 64x64 warp tile, m16n8k16.
// ---------------------------------------------------------------------------
#define ASTRH 40    // halfs per A row (32 + pad) -> 20 b32: conflict-free ldmatrix
#define BSTRH 136   // halfs per B row (128 + pad) -> 68 b32: conflict-free

__global__ __launch_bounds__(128)
void qkv_gemm_kernel(const float* __restrict__ X,
                     const float* __restrict__ W,
                     const float* __restrict__ bias) {
    __shared__ __half Ah[128 * ASTRH], Al[128 * ASTRH];   // [m][k]
    __shared__ __half Bh[32 * BSTRH],  Bl[32 * BSTRH];    // [k][n]

    const int tid = threadIdx.x;
    const int warp = tid >> 5, lane = tid & 31;
    const int g = lane >> 2, tg = lane & 3;
    const int lr = lane & 15;            // ldmatrix row-within-16
    const int lc = (lane & 16) >> 1;     // ldmatrix col offset 0/8
    const int wm = (warp & 1) * 64, wn = (warp >> 1) * 64;
    const int bm = blockIdx.y * 128, bn = blockIdx.x * 128;

    const unsigned ah_b = smem_u32(Ah), al_b = smem_u32(Al);
    const unsigned bh_b = smem_u32(Bh), bl_b = smem_u32(Bl);

    float acc[4][8][4];
#pragma unroll
    for (int mt = 0; mt < 4; mt++)
#pragma unroll
        for (int nt = 0; nt < 8; nt++)
#pragma unroll
            for (int i = 0; i < 4; i++) acc[mt][nt][i] = 0.f;

    for (int k0 = 0; k0 < 1024; k0 += 32) {
        // stage A [128m x 32k] (natural row-major)
#pragma unroll
        for (int r = 0; r < 8; r++) {
            int l = tid + 128 * r;
            int row = l >> 3, kc = (l & 7) << 2;
            float4 v = *(const float4*)(X + (size_t)(bm + row) * 1024 + k0 + kc);
            cvt_store(Ah, Al, row * ASTRH + kc, v);
        }
        // stage B [32k x 128n] (natural row-major)
#pragma unroll
        for (int r = 0; r < 8; r++) {
            int l = tid + 128 * r;
            int row = l >> 5, col = (l & 31) << 2;
            float4 v = *(const float4*)(W + (size_t)(k0 + row) * 3072 + bn + col);
            cvt_store(Bh, Bl, row * BSTRH + col, v);
        }
        __syncthreads();

#pragma unroll
        for (int ks = 0; ks < 2; ks++) {
            int kb = ks * 16;
            unsigned ahf[4][4], alf[4][4];
#pragma unroll
            for (int mt = 0; mt < 4; mt++) {
                unsigned off = (unsigned)((wm + mt * 16 + lr) * ASTRH + kb + lc) * 2u;
                ldm_x4(ahf[mt], ah_b + off);
                ldm_x4(alf[mt], al_b + off);
            }
#pragma unroll
            for (int nt2 = 0; nt2 < 4; nt2++) {
                unsigned off = (unsigned)((kb + lr) * BSTRH + wn + nt2 * 16 + lc) * 2u;
                unsigned bhr[4], blr[4];
                ldm_x4t(bhr, bh_b + off);   // trans: {b0,b1} nt, {b0,b1} nt+1
                ldm_x4t(blr, bl_b + off);
#pragma unroll
                for (int p = 0; p < 2; p++) {
                    int nt = nt2 * 2 + p;
                    unsigned bhp[2] = { bhr[2 * p], bhr[2 * p + 1] };
                    unsigned blp[2] = { blr[2 * p], blr[2 * p + 1] };
#pragma unroll
                    for (int mt = 0; mt < 4; mt++) {
                        mma16(acc[mt][nt], ahf[mt], bhp);   // hi*hi
                        mma16(acc[mt][nt], ahf[mt], blp);   // hi*lo
                        mma16(acc[mt][nt], alf[mt], bhp);   // lo*hi
                    }
                }
            }
        }
        __syncthreads();
    }

    // epilogue: bias + scatter
#pragma unroll
    for (int nt = 0; nt < 8; nt++) {
        int n0 = bn + wn + nt * 8 + 2 * tg;
        float bia0 = bias[n0], bia1 = bias[n0 + 1];
        int nh  = n0 / 192;
        int rem = n0 - nh * 192;
        int which = rem >> 6;
        int hd = rem & 63;
        float* basep = (which == 0) ? g_q : ((which == 1) ? g_k : g_v);
#pragma unroll
        for (int mt = 0; mt < 4; mt++) {
            int m0 = bm + wm + mt * 16 + g;
#pragma unroll
            for (int h = 0; h < 2; h++) {
                int m = m0 + h * 8;
                int b = m >> 10, s = m & 1023;
                float2 v;
                v.x = acc[mt][nt][h * 2 + 0] + bia0;
                v.y = acc[mt][nt][h * 2 + 1] + bia1;
                *(float2*)(basep + (((size_t)(b * NH_ + nh)) * S_ + s) * HD_ + hd) = v;
            }
        }
    }
}

// ---------------------------------------------------------------------------
// Kernel 2: fused flash attention. fp16x2x3 QK, fp16 P x fp16x2 V.
// Block = (b,h) x 128-query tile, 4 warps x 32 q. 16 key-tiles of 64.
// ---------------------------------------------------------------------------
#define QSH 72   // halfs per row (64 + 8 pad) -> 36 b32: conflict-free ldmatrix

__global__ __launch_bounds__(128)
void attn_kernel(const int* __restrict__ mask, float* __restrict__ out) {
    extern __shared__ char smc[];
    __half* Qh = (__half*)smc;          // [128][72]
    __half* Ql = Qh + 128 * QSH;
    __half* Kh = Ql + 128 * QSH;        // [64][72]
    __half* Kl = Kh + 64 * QSH;
    __half* Vh = Kl + 64 * QSH;         // [64][72]
    __half* Vl = Vh + 64 * QSH;
    __half* Ps = Vl + 64 * QSH;         // [128][72] fp16 probs
    int*    mk = (int*)(Ps + 128 * QSH);   // [1024]

    const int bh = blockIdx.y, b = bh >> 4, nh = bh & 15;
    const int q0 = blockIdx.x * 128;
    const int tid = threadIdx.x;
    const int warp = tid >> 5, lane = tid & 31;
    const int g = lane >> 2, tg = lane & 3;
    const int lr = lane & 15;
    const int lc = (lane & 16) >> 1;
    const int wq = warp * 32;

    const unsigned qh_b = smem_u32(Qh), ql_b = smem_u32(Ql);
    const unsigned kh_b = smem_u32(Kh), kl_b = smem_u32(Kl);
    const unsigned vh_b = smem_u32(Vh), vl_b = smem_u32(Vl);
    const unsigned ps_b = smem_u32(Ps);

    // load Q (x8 scale, exact power of 2) + mask
    const float* qg = g_q + ((size_t)bh * S_ + q0) * HD_;
#pragma unroll
    for (int r = 0; r < 16; r++) {
        int cc = tid + 128 * r;
        int q = cc >> 4, d = (cc & 15) << 2;
        float4 v = *(const float4*)(qg + q * 64 + d);
        v.x *= 8.f; v.y *= 8.f; v.z *= 8.f; v.w *= 8.f;
        cvt_store(Qh, Ql, q * QSH + d, v);
    }
#pragma unroll
    for (int r = 0; r < 8; r++) {
        int j = tid + 128 * r;
        mk[j] = mask[b * S_ + j];
    }

    float O[2][8][4];
    float mrow[2][2], lrow[2][2];
#pragma unroll
    for (int mt = 0; mt < 2; mt++) {
        mrow[mt][0] = -INFINITY; mrow[mt][1] = -INFINITY;
        lrow[mt][0] = 0.f;       lrow[mt][1] = 0.f;
#pragma unroll
        for (int nt = 0; nt < 8; nt++)
#pragma unroll
            for (int i = 0; i < 4; i++) O[mt][nt][i] = 0.f;
    }

    for (int kt = 0; kt < 16; kt++) {
        __syncthreads();   // Q/mask ready (kt=0); K/V consumers done (kt>0)
        const float* kg = g_k + ((size_t)bh * S_ + kt * 64) * HD_;
        const float* vg = g_v + ((size_t)bh * S_ + kt * 64) * HD_;
#pragma unroll
        for (int r = 0; r < 8; r++) {
            int cc = tid + 128 * r;
            int key = cc >> 4, d = (cc & 15) << 2;
            cvt_store(Kh, Kl, key * QSH + d, *(const float4*)(kg + key * 64 + d));
            cvt_store(Vh, Vl, key * QSH + d, *(const float4*)(vg + key * 64 + d));
        }
        __syncthreads();

        // ---- S = (Q*8) @ K^T  (fp16x2, 3 passes) ----
        float S[2][8][4];
#pragma unroll
        for (int mt = 0; mt < 2; mt++)
#pragma unroll
            for (int nt = 0; nt < 8; nt++)
#pragma unroll
                for (int i = 0; i < 4; i++) S[mt][nt][i] = 0.f;

#pragma unroll
        for (int ks = 0; ks < 4; ks++) {
            int kb = ks * 16;
            unsigned qhf[2][4], qlf[2][4];
#pragma unroll
            for (int mt = 0; mt < 2; mt++) {
                unsigned off = (unsigned)((wq + mt * 16 + lr) * QSH + kb + lc) * 2u;
                ldm_x4(qhf[mt], qh_b + off);
                ldm_x4(qlf[mt], ql_b + off);
            }
#pragma unroll
            for (int nt2 = 0; nt2 < 4; nt2++) {
                unsigned off = (unsigned)((nt2 * 16 + lr) * QSH + kb + lc) * 2u;
                unsigned khr[4], klr[4];
                ldm_x4(khr, kh_b + off);    // non-trans: {b0 nt, b0 nt+1, b1 nt, b1 nt+1}
                ldm_x4(klr, kl_b + off);
#pragma unroll
                for (int p = 0; p < 2; p++) {
                    int nt = nt2 * 2 + p;
                    unsigned bhp[2] = { khr[p], khr[p + 2] };
                    unsigned blp[2] = { klr[p], klr[p + 2] };
#pragma unroll
                    for (int mt = 0; mt < 2; mt++) {
                        mma16(S[mt][nt], qhf[mt], bhp);
                        mma16(S[mt][nt], qhf[mt], blp);
                        mma16(S[mt][nt], qlf[mt], bhp);
                    }
                }
            }
        }

        // ---- mask (mask!=0 -> -10000) ----
#pragma unroll
        for (int nt = 0; nt < 8; nt++) {
            int c = kt * 64 + nt * 8 + 2 * tg;
            if (mk[c]) {
                S[0][nt][0] = -10000.f; S[0][nt][2] = -10000.f;
                S[1][nt][0] = -10000.f; S[1][nt][2] = -10000.f;
            }
            if (mk[c + 1]) {
                S[0][nt][1] = -10000.f; S[0][nt][3] = -10000.f;
                S[1][nt][1] = -10000.f; S[1][nt][3] = -10000.f;
            }
        }

        // ---- online softmax (rows warp-local; reduce over tg quartet) ----
#pragma unroll
        for (int mt = 0; mt < 2; mt++)
#pragma unroll
        for (int h = 0; h < 2; h++) {
            float rm = -INFINITY;
#pragma unroll
            for (int nt = 0; nt < 8; nt++)
                rm = fmaxf(rm, fmaxf(S[mt][nt][2 * h], S[mt][nt][2 * h + 1]));
            rm = fmaxf(rm, __shfl_xor_sync(0xffffffffu, rm, 1));
            rm = fmaxf(rm, __shfl_xor_sync(0xffffffffu, rm, 2));
            float mn = fmaxf(mrow[mt][h], rm);
            float corr = __expf(mrow[mt][h] - mn);
            mrow[mt][h] = mn;
            float rs = 0.f;
#pragma unroll
            for (int nt = 0; nt < 8; nt++) {
                float e0 = __expf(S[mt][nt][2 * h] - mn);
                float e1 = __expf(S[mt][nt][2 * h + 1] - mn);
                S[mt][nt][2 * h] = e0; S[mt][nt][2 * h + 1] = e1;
                rs += e0 + e1;
            }
            rs += __shfl_xor_sync(0xffffffffu, rs, 1);
            rs += __shfl_xor_sync(0xffffffffu, rs, 2);
            lrow[mt][h] = lrow[mt][h] * corr + rs;
#pragma unroll
            for (int nt = 0; nt < 8; nt++) {
                O[mt][nt][2 * h]     *= corr;
                O[mt][nt][2 * h + 1] *= corr;
            }
        }

        // ---- stash P fp16 (warp-private rows) ----
#pragma unroll
        for (int mt = 0; mt < 2; mt++)
#pragma unroll
        for (int h = 0; h < 2; h++) {
            int row = wq + mt * 16 + g + h * 8;
#pragma unroll
            for (int nt = 0; nt < 8; nt++) {
                __half2 p2 = __float22half2_rn(
                    make_float2(S[mt][nt][2 * h], S[mt][nt][2 * h + 1]));
                *(__half2*)&Ps[row * QSH + nt * 8 + 2 * tg] = p2;
            }
        }
        __syncwarp();

        // ---- O += P @ V  (P single, V hi/lo: 2 passes) ----
#pragma unroll
        for (int ks = 0; ks < 4; ks++) {
            int kb = ks * 16;
            unsigned pf[2][4];
#pragma unroll
            for (int mt = 0; mt < 2; mt++) {
                unsigned off = (unsigned)((wq + mt * 16 + lr) * QSH + kb + lc) * 2u;
                ldm_x4(pf[mt], ps_b + off);
            }
#pragma unroll
            for (int nt2 = 0; nt2 < 4; nt2++) {
                unsigned off = (unsigned)((kb + lr) * QSH + nt2 * 16 + lc) * 2u;
                unsigned vhr[4], vlr[4];
                ldm_x4t(vhr, vh_b + off);   // trans: {b0,b1} nt, {b0,b1} nt+1
                ldm_x4t(vlr, vl_b + off);
#pragma unroll
                for (int p = 0; p < 2; p++) {
                    int nt = nt2 * 2 + p;
                    unsigned bhp[2] = { vhr[2 * p], vhr[2 * p + 1] };
                    unsigned blp[2] = { vlr[2 * p], vlr[2 * p + 1] };
#pragma unroll
                    for (int mt = 0; mt < 2; mt++) {
                        mma16(O[mt][nt], pf[mt], bhp);
                        mma16(O[mt][nt], pf[mt], blp);
                    }
                }
            }
        }
    }

    // epilogue: out[b, q, nh*64 + d]
#pragma unroll
    for (int mt = 0; mt < 2; mt++)
#pragma unroll
    for (int h = 0; h < 2; h++) {
        float inv = 1.f / lrow[mt][h];
        int q = q0 + wq + mt * 16 + g + h * 8;
        float* op = out + ((size_t)(b * S_ + q)) * H_ + nh * 64;
#pragma unroll
        for (int nt = 0; nt < 8; nt++) {
            float2 v;
            v.x = O[mt][nt][2 * h] * inv;
            v.y = O[mt][nt][2 * h + 1] * inv;
            *(float2*)(op + nt * 8 + 2 * tg) = v;
        }
    }
}

// ---------------------------------------------------------------------------
extern "C" void kernel_launch(void* const* d_in, const int* in_sizes, int n_in,
                              void* d_out, int out_size) {
    const float* hidden = (const float*)d_in[0];   // [8,1024,1024]
    const int*   mask   = (const int*)  d_in[1];   // [8,1,1,1024]
    const float* w_qkv  = (const float*)d_in[2];   // [1024,3072]
    const float* b_qkv  = (const float*)d_in[3];   // [3072]
    float* out = (float*)d_out;

    (void)in_sizes; (void)n_in; (void)out_size;

    dim3 g1(3072 / 128, 8192 / 128);               // 24 x 64
    qkv_gemm_kernel<<<g1, 128>>>(hidden, w_qkv, b_qkv);

    // smem: (Q hi+lo + Ps) 128*72*3 + (K,V hi+lo) 64*72*4 halfs + mask
    size_t smem = (size_t)(128 * QSH * 3 + 64 * QSH * 4) * sizeof(__half)
                + 1024 * sizeof(int);              // 96256 B
    cudaFuncSetAttribute(attn_kernel, cudaFuncAttributeMaxDynamicSharedMemorySize,
                         (int)smem);
    dim3 g2(S_ / 128, BH_);                         // 8 x 128
    attn_kernel<<<g2, 128, smem>>>(mask, out);
}

// round 7
// speedup vs baseline: 3.2840x; 1.0038x over previous
#include <cuda_runtime.h>
#include <cuda_fp16.h>
#include <math.h>
#include <stdint.h>

#define B_  8
#define S_  1024
#define H_  1024
#define NH_ 16
#define HD_ 64
#define BH_ (B_*NH_)   // 128

// fp16 hi/lo split scratch (all row-major halfs)
__device__ __half g_xh[(size_t)8192*1024];
__device__ __half g_xl[(size_t)8192*1024];
__device__ __half g_wh[(size_t)1024*3072];
__device__ __half g_wl[(size_t)1024*3072];
__device__ __half g_qh[(size_t)BH_*S_*HD_];   // pre-scaled x8
__device__ __half g_ql[(size_t)BH_*S_*HD_];
__device__ __half g_kh[(size_t)BH_*S_*HD_];
__device__ __half g_kl[(size_t)BH_*S_*HD_];
__device__ __half g_vh[(size_t)BH_*S_*HD_];
__device__ __half g_vl[(size_t)BH_*S_*HD_];

// ---------------------------------------------------------------------------
// helpers
// ---------------------------------------------------------------------------
__device__ __forceinline__ unsigned smem_u32(const void* p) {
    return (unsigned)__cvta_generic_to_shared(p);
}
__device__ __forceinline__ void ldm_x4(unsigned* r, unsigned addr) {
    asm volatile("ldmatrix.sync.aligned.m8n8.x4.shared.b16 {%0,%1,%2,%3}, [%4];"
        : "=r"(r[0]), "=r"(r[1]), "=r"(r[2]), "=r"(r[3]) : "r"(addr));
}
__device__ __forceinline__ void ldm_x4t(unsigned* r, unsigned addr) {
    asm volatile("ldmatrix.sync.aligned.m8n8.x4.trans.shared.b16 {%0,%1,%2,%3}, [%4];"
        : "=r"(r[0]), "=r"(r[1]), "=r"(r[2]), "=r"(r[3]) : "r"(addr));
}
__device__ __forceinline__ void mma16(float* d, const unsigned* a, const unsigned* b) {
    asm volatile(
        "mma.sync.aligned.m16n8k16.row.col.f32.f16.f16.f32 "
        "{%0,%1,%2,%3}, {%4,%5,%6,%7}, {%8,%9}, {%0,%1,%2,%3};\n"
        : "+f"(d[0]), "+f"(d[1]), "+f"(d[2]), "+f"(d[3])
        : "r"(a[0]), "r"(a[1]), "r"(a[2]), "r"(a[3]), "r"(b[0]), "r"(b[1]));
}
#define CP16(dst, src) \
    asm volatile("cp.async.cg.shared.global [%0], [%1], 16;" \
                 :: "r"((uint32_t)(dst)), "l"(src) : "memory")
#define CP_COMMIT() asm volatile("cp.async.commit_group;" ::: "memory")
#define CP_WAIT(n)  asm volatile("cp.async.wait_group %0;" :: "n"(n) : "memory")

__device__ __forceinline__ void split_h2(float x, float y, __half2& h, __half2& l) {
    h = __float22half2_rn(make_float2(x, y));
    float2 f = __half22float2(h);
    l = __float22half2_rn(make_float2(x - f.x, y - f.y));
}

// ---------------------------------------------------------------------------
// Kernel 0: preconvert X and W to fp16 hi/lo
// ---------------------------------------------------------------------------
#define NX4 2097152   // 8M floats / 4
#define NW4 786432    // 3M floats / 4
__global__ __launch_bounds__(256)
void preconv_kernel(const float* __restrict__ X, const float* __restrict__ W) {
    int idx = blockIdx.x * 256 + threadIdx.x;
    if (idx < NX4) {
        float4 v = ((const float4*)X)[idx];
        __half2 h0, l0, h1, l1;
        split_h2(v.x, v.y, h0, l0);
        split_h2(v.z, v.w, h1, l1);
        *(__half2*)(g_xh + idx * 4)     = h0;
        *(__half2*)(g_xh + idx * 4 + 2) = h1;
        *(__half2*)(g_xl + idx * 4)     = l0;
        *(__half2*)(g_xl + idx * 4 + 2) = l1;
    } else if (idx < NX4 + NW4) {
        int j = idx - NX4;
        float4 v = ((const float4*)W)[j];
        __half2 h0, l0, h1, l1;
        split_h2(v.x, v.y, h0, l0);
        split_h2(v.z, v.w, h1, l1);
        *(__half2*)(g_wh + j * 4)     = h0;
        *(__half2*)(g_wh + j * 4 + 2) = h1;
        *(__half2*)(g_wl + j * 4)     = l0;
        *(__half2*)(g_wl + j * 4 + 2) = l1;
    }
}

// ---------------------------------------------------------------------------
// Kernel 1: QKV GEMM (fp16 hi/lo, 3 passes), cp.async double-buffered.
// 128x128x32 tile, 256 threads (8 warps, 32x64 warp tile).
// Epilogue: bias, scatter to g_{q,k,v}{h,l} (Q pre-scaled x8).
// ---------------------------------------------------------------------------
#define ASTRH 40
#define BSTRH 136
#define A_BYTES (128 * ASTRH * 2)   // 10240
#define B_BYTES (32 * BSTRH * 2)    // 8704
#define BUFB (2 * A_BYTES + 2 * B_BYTES)   // 37888

__global__ __launch_bounds__(256, 2)
void qkv_gemm_kernel(const float* __restrict__ bias) {
    extern __shared__ __align__(16) char smem[];

    const int tid = threadIdx.x;
    const int warp = tid >> 5, lane = tid & 31;
    const int g = lane >> 2, tg = lane & 3;
    const int lr = lane & 15;
    const int lc = (lane & 16) >> 1;
    const int wm = (warp & 3) * 32, wn = (warp >> 2) * 64;
    const int bm = blockIdx.y * 128, bn = blockIdx.x * 128;

    float acc[2][8][4];
#pragma unroll
    for (int mt = 0; mt < 2; mt++)
#pragma unroll
        for (int nt = 0; nt < 8; nt++)
#pragma unroll
            for (int i = 0; i < 4; i++) acc[mt][nt][i] = 0.f;

    // stage chunk c into buffer buf
    auto stage = [&](int c, int buf) {
        const int k0 = c * 32;
        uint32_t base = smem_u32(smem) + buf * BUFB;
        uint32_t ah = base, al = base + A_BYTES;
        uint32_t bh = base + 2 * A_BYTES, bl = bh + B_BYTES;
#pragma unroll
        for (int r = 0; r < 2; r++) {
            int l = tid + 256 * r;          // 0..511
            int row = l >> 2, c4 = l & 3;   // A: 128 rows x 4 chunks of 8 halfs
            size_t src = (size_t)(bm + row) * 1024 + k0 + c4 * 8;
            uint32_t d = (uint32_t)(row * ASTRH + c4 * 8) * 2;
            CP16(ah + d, g_xh + src);
            CP16(al + d, g_xl + src);
        }
#pragma unroll
        for (int r = 0; r < 2; r++) {
            int l = tid + 256 * r;
            int row = l >> 4, c16 = l & 15; // B: 32 rows x 16 chunks
            size_t src = (size_t)(k0 + row) * 3072 + bn + c16 * 8;
            uint32_t d = (uint32_t)(row * BSTRH + c16 * 8) * 2;
            CP16(bh + d, g_wh + src);
            CP16(bl + d, g_wl + src);
        }
    };

    stage(0, 0);
    CP_COMMIT();

    for (int c = 0; c < 32; c++) {
        const int buf = c & 1;
        if (c + 1 < 32) {
            stage(c + 1, buf ^ 1);
            CP_COMMIT();
            CP_WAIT(1);
        } else {
            CP_WAIT(0);
        }
        __syncthreads();

        uint32_t base = smem_u32(smem) + buf * BUFB;
        uint32_t ah = base, al = base + A_BYTES;
        uint32_t bh = base + 2 * A_BYTES, bl = bh + B_BYTES;

#pragma unroll
        for (int ks = 0; ks < 2; ks++) {
            int kb = ks * 16;
            unsigned ahf[2][4], alf[2][4];
#pragma unroll
            for (int mt = 0; mt < 2; mt++) {
                uint32_t off = (uint32_t)((wm + mt * 16 + lr) * ASTRH + kb + lc) * 2;
                ldm_x4(ahf[mt], ah + off);
                ldm_x4(alf[mt], al + off);
            }
#pragma unroll
            for (int nt2 = 0; nt2 < 4; nt2++) {
                uint32_t off = (uint32_t)((kb + lr) * BSTRH + wn + nt2 * 16 + lc) * 2;
                unsigned bhr[4], blr[4];
                ldm_x4t(bhr, bh + off);
                ldm_x4t(blr, bl + off);
#pragma unroll
                for (int p = 0; p < 2; p++) {
                    int nt = nt2 * 2 + p;
                    unsigned bhp[2] = { bhr[2 * p], bhr[2 * p + 1] };
                    unsigned blp[2] = { blr[2 * p], blr[2 * p + 1] };
#pragma unroll
                    for (int mt = 0; mt < 2; mt++) {
                        mma16(acc[mt][nt], ahf[mt], bhp);   // hi*hi
                        mma16(acc[mt][nt], ahf[mt], blp);   // hi*lo
                        mma16(acc[mt][nt], alf[mt], bhp);   // lo*hi
                    }
                }
            }
        }
        __syncthreads();   // all warps done reading before overwrite
    }

    // epilogue: bias + hi/lo split + scatter
#pragma unroll
    for (int nt = 0; nt < 8; nt++) {
        int n0 = bn + wn + nt * 8 + 2 * tg;
        float bia0 = bias[n0], bia1 = bias[n0 + 1];
        int nh  = n0 / 192;
        int rem = n0 - nh * 192;
        int which = rem >> 6;
        int hd = rem & 63;
        __half* ph = (which == 0) ? g_qh : ((which == 1) ? g_kh : g_vh);
        __half* pl = (which == 0) ? g_ql : ((which == 1) ? g_kl : g_vl);
        float sc = (which == 0) ? 8.f : 1.f;
#pragma unroll
        for (int mt = 0; mt < 2; mt++) {
#pragma unroll
            for (int h = 0; h < 2; h++) {
                int m = bm + wm + mt * 16 + g + h * 8;
                int b = m >> 10, s = m & 1023;
                float vx = (acc[mt][nt][h * 2 + 0] + bia0) * sc;
                float vy = (acc[mt][nt][h * 2 + 1] + bia1) * sc;
                __half2 hh, ll;
                split_h2(vx, vy, hh, ll);
                size_t dst = (((size_t)(b * NH_ + nh)) * S_ + s) * HD_ + hd;
                *(__half2*)(ph + dst) = hh;
                *(__half2*)(pl + dst) = ll;
            }
        }
    }
}

// ---------------------------------------------------------------------------
// Kernel 2: fused flash attention. 256 threads (8 warps x 16 queries).
// 128-query tile, 16 key-tiles of 64. fp16x3 QK, fp16 P x fp16x2 V.
// All operands staged by cp.async from preconverted fp16 arrays.
// ---------------------------------------------------------------------------
#define QSH 72

__global__ __launch_bounds__(256, 2)
void attn_kernel(const int* __restrict__ mask, float* __restrict__ out) {
    extern __shared__ char smc[];
    __half* Qh = (__half*)smc;          // [128][72]
    __half* Ql = Qh + 128 * QSH;
    __half* Kh = Ql + 128 * QSH;        // [64][72]
    __half* Kl = Kh + 64 * QSH;
    __half* Vh = Kl + 64 * QSH;         // [64][72]
    __half* Vl = Vh + 64 * QSH;
    __half* Ps = Vl + 64 * QSH;         // [128][72]
    int*    mk = (int*)(Ps + 128 * QSH);   // [1024]

    const int bh = blockIdx.y, b = bh >> 4, nh = bh & 15;
    const int q0 = blockIdx.x * 128;
    const int tid = threadIdx.x;
    const int warp = tid >> 5, lane = tid & 31;
    const int g = lane >> 2, tg = lane & 3;
    const int lr = lane & 15;
    const int lc = (lane & 16) >> 1;
    const int wq = warp * 16;

    const unsigned qh_b = smem_u32(Qh), ql_b = smem_u32(Ql);
    const unsigned kh_b = smem_u32(Kh), kl_b = smem_u32(Kl);
    const unsigned vh_b = smem_u32(Vh), vl_b = smem_u32(Vl);
    const unsigned ps_b = smem_u32(Ps);

    // stage Q (pre-scaled) via cp.async + mask via ld
    // Q: 128 rows x 64 halfs = 128 rows x 8 chunks of 16B -> 1024 CP16 per array
    {
        const size_t qbase = ((size_t)bh * S_ + q0) * HD_;
#pragma unroll
        for (int r = 0; r < 4; r++) {
            int l = tid + 256 * r;          // 0..1023
            int row = l >> 3, c8 = l & 7;   // 128 rows x 8 chunks
            size_t src = qbase + row * 64 + c8 * 8;
            uint32_t d = (uint32_t)(row * QSH + c8 * 8) * 2;
            CP16(qh_b + d, g_qh + src);
            CP16(ql_b + d, g_ql + src);
        }
        CP_COMMIT();
        *(int4*)&mk[tid * 4] = *(const int4*)&mask[b * S_ + tid * 4];
    }

    float O[8][4];
    float mrow[2], lrow[2];
    mrow[0] = -INFINITY; mrow[1] = -INFINITY;
    lrow[0] = 0.f;       lrow[1] = 0.f;
#pragma unroll
    for (int nt = 0; nt < 8; nt++)
#pragma unroll
        for (int i = 0; i < 4; i++) O[nt][i] = 0.f;

    for (int kt = 0; kt < 16; kt++) {
        __syncthreads();   // consumers of previous K/V done
        // K/V: 64 rows x 8 chunks = 512 CP16 per array
        {
            const size_t kbase = ((size_t)bh * S_ + kt * 64) * HD_;
#pragma unroll
            for (int r = 0; r < 2; r++) {
                int l = tid + 256 * r;          // 0..511
                int row = l >> 3, c8 = l & 7;   // 64 rows x 8 chunks
                size_t src = kbase + row * 64 + c8 * 8;
                uint32_t d = (uint32_t)(row * QSH + c8 * 8) * 2;
                CP16(kh_b + d, g_kh + src);
                CP16(kl_b + d, g_kl + src);
                CP16(vh_b + d, g_vh + src);
                CP16(vl_b + d, g_vl + src);
            }
        }
        CP_COMMIT();
        CP_WAIT(0);
        __syncthreads();

        // ---- S = Q @ K^T (3 passes) ----
        float S[8][4];
#pragma unroll
        for (int nt = 0; nt < 8; nt++)
#pragma unroll
            for (int i = 0; i < 4; i++) S[nt][i] = 0.f;

#pragma unroll
        for (int ks = 0; ks < 4; ks++) {
            int kb = ks * 16;
            unsigned qhf[4], qlf[4];
            {
                uint32_t off = (uint32_t)((wq + lr) * QSH + kb + lc) * 2;
                ldm_x4(qhf, qh_b + off);
                ldm_x4(qlf, ql_b + off);
            }
#pragma unroll
            for (int nt2 = 0; nt2 < 4; nt2++) {
                uint32_t off = (uint32_t)((nt2 * 16 + lr) * QSH + kb + lc) * 2;
                unsigned khr[4], klr[4];
                ldm_x4(khr, kh_b + off);
                ldm_x4(klr, kl_b + off);
#pragma unroll
                for (int p = 0; p < 2; p++) {
                    int nt = nt2 * 2 + p;
                    unsigned bhp[2] = { khr[p], khr[p + 2] };
                    unsigned blp[2] = { klr[p], klr[p + 2] };
                    mma16(S[nt], qhf, bhp);
                    mma16(S[nt], qhf, blp);
                    mma16(S[nt], qlf, bhp);
                }
            }
        }

        // ---- mask ----
#pragma unroll
        for (int nt = 0; nt < 8; nt++) {
            int c = kt * 64 + nt * 8 + 2 * tg;
            if (mk[c])     { S[nt][0] = -10000.f; S[nt][2] = -10000.f; }
            if (mk[c + 1]) { S[nt][1] = -10000.f; S[nt][3] = -10000.f; }
        }

        // ---- online softmax ----
#pragma unroll
        for (int h = 0; h < 2; h++) {
            float rm = -INFINITY;
#pragma unroll
            for (int nt = 0; nt < 8; nt++)
                rm = fmaxf(rm, fmaxf(S[nt][2 * h], S[nt][2 * h + 1]));
            rm = fmaxf(rm, __shfl_xor_sync(0xffffffffu, rm, 1));
            rm = fmaxf(rm, __shfl_xor_sync(0xffffffffu, rm, 2));
            float mn = fmaxf(mrow[h], rm);
            float corr = __expf(mrow[h] - mn);
            mrow[h] = mn;
            float rs = 0.f;
#pragma unroll
            for (int nt = 0; nt < 8; nt++) {
                float e0 = __expf(S[nt][2 * h] - mn);
                float e1 = __expf(S[nt][2 * h + 1] - mn);
                S[nt][2 * h] = e0; S[nt][2 * h + 1] = e1;
                rs += e0 + e1;
            }
            rs += __shfl_xor_sync(0xffffffffu, rs, 1);
            rs += __shfl_xor_sync(0xffffffffu, rs, 2);
            lrow[h] = lrow[h] * corr + rs;
#pragma unroll
            for (int nt = 0; nt < 8; nt++) {
                O[nt][2 * h]     *= corr;
                O[nt][2 * h + 1] *= corr;
            }
        }

        // ---- stash P fp16 (warp-private rows) ----
#pragma unroll
        for (int h = 0; h < 2; h++) {
            int row = wq + g + h * 8;
#pragma unroll
            for (int nt = 0; nt < 8; nt++) {
                __half2 p2 = __float22half2_rn(
                    make_float2(S[nt][2 * h], S[nt][2 * h + 1]));
                *(__half2*)&Ps[row * QSH + nt * 8 + 2 * tg] = p2;
            }
        }
        __syncwarp();

        // ---- O += P @ V (V hi/lo 2 passes) ----
#pragma unroll
        for (int ks = 0; ks < 4; ks++) {
            int kb = ks * 16;
            unsigned pf[4];
            {
                uint32_t off = (uint32_t)((wq + lr) * QSH + kb + lc) * 2;
                ldm_x4(pf, ps_b + off);
            }
#pragma unroll
            for (int nt2 = 0; nt2 < 4; nt2++) {
                uint32_t off = (uint32_t)((kb + lr) * QSH + nt2 * 16 + lc) * 2;
                unsigned vhr[4], vlr[4];
                ldm_x4t(vhr, vh_b + off);
                ldm_x4t(vlr, vl_b + off);
#pragma unroll
                for (int p = 0; p < 2; p++) {
                    int nt = nt2 * 2 + p;
                    unsigned bhp[2] = { vhr[2 * p], vhr[2 * p + 1] };
                    unsigned blp[2] = { vlr[2 * p], vlr[2 * p + 1] };
                    mma16(O[nt], pf, bhp);
                    mma16(O[nt], pf, blp);
                }
            }
        }
    }

    // epilogue
#pragma unroll
    for (int h = 0; h < 2; h++) {
        float inv = 1.f / lrow[h];
        int q = q0 + wq + g + h * 8;
        float* op = out + ((size_t)(b * S_ + q)) * H_ + nh * 64;
#pragma unroll
        for (int nt = 0; nt < 8; nt++) {
            float2 v;
            v.x = O[nt][2 * h] * inv;
            v.y = O[nt][2 * h + 1] * inv;
            *(float2*)(op + nt * 8 + 2 * tg) = v;
        }
    }
}

// ---------------------------------------------------------------------------
extern "C" void kernel_launch(void* const* d_in, const int* in_sizes, int n_in,
                              void* d_out, int out_size) {
    const float* hidden = (const float*)d_in[0];   // [8,1024,1024]
    const int*   mask   = (const int*)  d_in[1];   // [8,1,1,1024]
    const float* w_qkv  = (const float*)d_in[2];   // [1024,3072]
    const float* b_qkv  = (const float*)d_in[3];   // [3072]
    float* out = (float*)d_out;

    (void)in_sizes; (void)n_in; (void)out_size;

    // 0: preconvert X, W -> fp16 hi/lo
    int n4 = NX4 + NW4;
    preconv_kernel<<<(n4 + 255) / 256, 256>>>(hidden, w_qkv);

    // 1: QKV GEMM
    size_t smem1 = 2 * (size_t)BUFB;               // 75776
    cudaFuncSetAttribute(qkv_gemm_kernel,
                         cudaFuncAttributeMaxDynamicSharedMemorySize, (int)smem1);
    dim3 g1(3072 / 128, 8192 / 128);               // 24 x 64
    qkv_gemm_kernel<<<g1, 256, smem1>>>(b_qkv);

    // 2: attention
    size_t smem2 = (size_t)(128 * QSH * 3 + 64 * QSH * 4) * sizeof(__half)
                 + 1024 * sizeof(int);             // 96256
    cudaFuncSetAttribute(attn_kernel,
                         cudaFuncAttributeMaxDynamicSharedMemorySize, (int)smem2);
    dim3 g2(S_ / 128, BH_);                         // 8 x 128
    attn_kernel<<<g2, 256, smem2>>>(mask, out);
}